// round 6
// baseline (speedup 1.0000x reference)
#include <cuda_runtime.h>

#define A_NUM 5
#define EPSV 1e-10f

// ---------------- batch-independent precomputed parameters ----------------
__device__ float g_Qt[64];
__device__ float g_G[64];   // Qt @ Qr
__device__ float g_Qy[64];
__device__ float g_wr[A_NUM];
__device__ float g_wz[A_NUM];  // ws[a] * (1 - alpha[a])
__device__ float g_c;          // sum_a ws[a] * alpha[a]
__device__ float g_t;

// 8x8 Cayley transform: Q = inv(I - Bm) @ (I + Bm), Bm = L - L^T,
// L[i+1][c] = b[i+c] for c in [0, i]  (reference's mapping).
__device__ void cayley8(const float* __restrict__ b, float* __restrict__ Q) {
    float Bm[8][8];
    for (int i = 0; i < 8; i++)
        for (int j = 0; j < 8; j++) Bm[i][j] = 0.0f;
    for (int i = 0; i < 7; i++)
        for (int c = 0; c <= i; c++) Bm[i + 1][c] = b[i + c];

    float A[8][16];
    for (int i = 0; i < 8; i++) {
        for (int j = 0; j < 8; j++) {
            float v = Bm[i][j] - Bm[j][i];
            float d = (i == j) ? 1.0f : 0.0f;
            A[i][j]     = d - v;   // I - Bm
            A[i][j + 8] = d + v;   // I + Bm
        }
    }
    for (int k = 0; k < 8; k++) {
        int p = k;
        float best = fabsf(A[k][k]);
        for (int r = k + 1; r < 8; r++) {
            float v = fabsf(A[r][k]);
            if (v > best) { best = v; p = r; }
        }
        if (p != k) {
            for (int j = 0; j < 16; j++) {
                float tmp = A[k][j]; A[k][j] = A[p][j]; A[p][j] = tmp;
            }
        }
        float inv = 1.0f / A[k][k];
        for (int j = 0; j < 16; j++) A[k][j] *= inv;
        for (int r = 0; r < 8; r++) {
            if (r == k) continue;
            float f = A[r][k];
            for (int j = 0; j < 16; j++) A[r][j] -= f * A[k][j];
        }
    }
    for (int i = 0; i < 8; i++)
        for (int j = 0; j < 8; j++) Q[i * 8 + j] = A[i][j + 8];
}

__global__ void spdsru_prologue(const float* __restrict__ kr,
                                const float* __restrict__ kt,
                                const float* __restrict__ kphi,
                                const float* __restrict__ ks,
                                const float* __restrict__ br,
                                const float* __restrict__ bt,
                                const float* __restrict__ by) {
    __shared__ float sQr[64];
    __shared__ float sQt[64];
    int tid = threadIdx.x;
    if (tid < 3) {
        const float* bias = (tid == 0) ? br : ((tid == 1) ? bt : by);
        float Q[64];
        cayley8(bias, Q);
        if (tid == 0) {
            for (int i = 0; i < 64; i++) sQr[i] = Q[i];
        } else if (tid == 1) {
            for (int i = 0; i < 64; i++) { sQt[i] = Q[i]; g_Qt[i] = Q[i]; }
        } else {
            for (int i = 0; i < 64; i++) g_Qy[i] = Q[i];
        }
    }
    __syncthreads();
    if (tid == 0) {
        for (int i = 0; i < 8; i++) {
            for (int j = 0; j < 8; j++) {
                float s = 0.0f;
                for (int k = 0; k < 8; k++) s += sQt[i * 8 + k] * sQr[k * 8 + j];
                g_G[i * 8 + j] = s;
            }
        }
        const float alpha[A_NUM] = {0.01f, 0.25f, 0.5f, 0.9f, 0.99f};
        float r2[A_NUM], s2[A_NUM], sr = 0.0f, ss = 0.0f;
        for (int a = 0; a < A_NUM; a++) {
            r2[a] = kr[a] * kr[a]; sr += r2[a];
            s2[a] = ks[a] * ks[a]; ss += s2[a];
        }
        float ir = 1.0f / (sr + EPSV);
        float is = 1.0f / (ss + EPSV);
        float c = 0.0f;
        for (int a = 0; a < A_NUM; a++) {
            g_wr[a] = r2[a] * ir;
            float ws = s2[a] * is;
            g_wz[a] = ws * (1.0f - alpha[a]);
            c += ws * alpha[a];
        }
        g_c = c;
        float t2 = kt[0] * kt[0];
        g_t = t2 / (t2 + kphi[0] * kphi[0] + EPSV);
    }
}

// ---------------- main streaming kernel ----------------
// 128 threads/block = 16 batch elements; thread j of each 8-thread group owns
// row j of every 8x8 matrix. States are NOT kept in registers: pass 1 streams
// them into the two reductions (yt, zt); pass 2 re-reads them (L2 hits) to
// produce the Mt outputs. St = zt + c*Phit by linearity -> no m needed live.
//
// Congruence C = Q*A*Q^T:
//   stage 1: B_row_j = A_row_j * Q^T   (Q rows broadcast via LDS.128, 1 wf ea)
//   stage 2: row j -> sB (STS.128), syncwarp,
//            C_row_j = sum_i Q[j][i] * B_row_i  (scalar padded-Q reads).

struct SQ {
    float4 packed[16];  // Q row-major as float4 pairs (broadcast reads)
    float  padded[72];  // Q row-major stride 9 (per-row scalar reads)
};

__device__ __forceinline__ void congruence8(const float* a,
                                            const SQ* Q,
                                            int j,
                                            float* bufbase,  // smem group tile (72 floats)
                                            float* c) {
    float bb[8];
#pragma unroll
    for (int k = 0; k < 8; k++) {
        float4 q0 = Q->packed[2 * k];
        float4 q1 = Q->packed[2 * k + 1];
        float s = a[0] * q0.x;
        s = fmaf(a[1], q0.y, s);
        s = fmaf(a[2], q0.z, s);
        s = fmaf(a[3], q0.w, s);
        s = fmaf(a[4], q1.x, s);
        s = fmaf(a[5], q1.y, s);
        s = fmaf(a[6], q1.z, s);
        s = fmaf(a[7], q1.w, s);
        bb[k] = s;
    }
    __syncwarp();   // previous congruence's reads of this buffer are done
    float4* bw = reinterpret_cast<float4*>(bufbase + j * 8);
    bw[0] = make_float4(bb[0], bb[1], bb[2], bb[3]);
    bw[1] = make_float4(bb[4], bb[5], bb[6], bb[7]);
    __syncwarp();   // all 8 rows visible before gathering
#pragma unroll
    for (int k = 0; k < 8; k++) c[k] = 0.0f;
#pragma unroll
    for (int i = 0; i < 8; i++) {
        float qji = Q->padded[j * 9 + i];
        const float4* br = reinterpret_cast<const float4*>(bufbase + i * 8);
        float4 b0 = br[0];
        float4 b1 = br[1];
        c[0] = fmaf(qji, b0.x, c[0]);
        c[1] = fmaf(qji, b0.y, c[1]);
        c[2] = fmaf(qji, b0.z, c[2]);
        c[3] = fmaf(qji, b0.w, c[3]);
        c[4] = fmaf(qji, b1.x, c[4]);
        c[5] = fmaf(qji, b1.y, c[5]);
        c[6] = fmaf(qji, b1.z, c[6]);
        c[7] = fmaf(qji, b1.w, c[7]);
    }
}

__global__ void __launch_bounds__(128, 8)
spdsru_main(const float* __restrict__ x,
            const float* __restrict__ states,
            float* __restrict__ out,
            float* __restrict__ outst) {
    __shared__ SQ sQt, sG, sQy;
    __shared__ float sB[16 * 72];   // 4 warps * 4 groups * 72 floats
    __shared__ float swr[A_NUM], swz[A_NUM];
    __shared__ float sgate, sc;

    const int tid = threadIdx.x;
    if (tid < 64) {
        int r = tid >> 3, cc = tid & 7;
        float qt = g_Qt[tid], gg = g_G[tid], qy = g_Qy[tid];
        reinterpret_cast<float*>(sQt.packed)[tid] = qt;
        reinterpret_cast<float*>(sG.packed)[tid]  = gg;
        reinterpret_cast<float*>(sQy.packed)[tid] = qy;
        sQt.padded[r * 9 + cc] = qt;
        sG.padded[r * 9 + cc]  = gg;
        sQy.padded[r * 9 + cc] = qy;
    } else if (tid < 64 + A_NUM) {
        swr[tid - 64] = g_wr[tid - 64];
        swz[tid - 64] = g_wz[tid - 64];
    } else if (tid == 70) {
        sgate = g_t;
        sc = g_c;
    }
    __syncthreads();

    const int grp = tid >> 3;            // 0..15
    const int j = tid & 7;
    const size_t b = (size_t)blockIdx.x * 16 + grp;
    float* bufbase = sB + grp * 72;

    // ---- load x row ----
    const float4* xp = reinterpret_cast<const float4*>(x + b * 64 + j * 8);
    float4 xa = xp[0], xb = xp[1];
    float xr[8] = {xa.x, xa.y, xa.z, xa.w, xb.x, xb.y, xb.z, xb.w};

    // ---- pass 1 over states: accumulate Yt and Zt, nothing stays live ----
    const float* mrow = states + b * 320 + j * 8;
    float yt[8], zt[8];
#pragma unroll
    for (int k = 0; k < 8; k++) { yt[k] = 0.0f; zt[k] = 0.0f; }
#pragma unroll
    for (int a = 0; a < A_NUM; a++) {
        const float4* mp = reinterpret_cast<const float4*>(mrow + a * 64);
        float4 m0 = mp[0], m1 = mp[1];
        float wa = swr[a], za = swz[a];
        yt[0] = fmaf(wa, m0.x, yt[0]);  zt[0] = fmaf(za, m0.x, zt[0]);
        yt[1] = fmaf(wa, m0.y, yt[1]);  zt[1] = fmaf(za, m0.y, zt[1]);
        yt[2] = fmaf(wa, m0.z, yt[2]);  zt[2] = fmaf(za, m0.z, zt[2]);
        yt[3] = fmaf(wa, m0.w, yt[3]);  zt[3] = fmaf(za, m0.w, zt[3]);
        yt[4] = fmaf(wa, m1.x, yt[4]);  zt[4] = fmaf(za, m1.x, zt[4]);
        yt[5] = fmaf(wa, m1.y, yt[5]);  zt[5] = fmaf(za, m1.y, zt[5]);
        yt[6] = fmaf(wa, m1.z, yt[6]);  zt[6] = fmaf(za, m1.z, zt[6]);
        yt[7] = fmaf(wa, m1.w, yt[7]);  zt[7] = fmaf(za, m1.w, zt[7]);
    }

    // ---- U = Qt*Xt*Qt^T ;  V = G*Yt*G^T  (G = Qt*Qr) ----
    float u[8], v[8];
    congruence8(xr, &sQt, j, bufbase, u);
    congruence8(yt, &sG, j, bufbase, v);

    // ---- Phit = (1-t)*U + t*V ----
    const float t = sgate;
    float phit[8];
#pragma unroll
    for (int k = 0; k < 8; k++) phit[k] = fmaf(t, v[k] - u[k], u[k]);

    // ---- St = Zt + c*Phit ;  Ot = Qy*St*Qy^T ; write output ----
    const float c = sc;
    float st[8];
#pragma unroll
    for (int k = 0; k < 8; k++) st[k] = fmaf(c, phit[k], zt[k]);

    float ot[8];
    congruence8(st, &sQy, j, bufbase, ot);
    float4* oo = reinterpret_cast<float4*>(out + b * 64 + j * 8);
    oo[0] = make_float4(ot[0], ot[1], ot[2], ot[3]);
    oo[1] = make_float4(ot[4], ot[5], ot[6], ot[7]);

    // ---- pass 2 over states (L2 hits): Mt[a] = m + alpha*(Phit - m) ----
    const float alpha[A_NUM] = {0.01f, 0.25f, 0.5f, 0.9f, 0.99f};
    float* orow = outst + b * 320 + j * 8;
#pragma unroll
    for (int a = 0; a < A_NUM; a++) {
        const float4* mp = reinterpret_cast<const float4*>(mrow + a * 64);
        float4 m0 = mp[0], m1 = mp[1];
        float aa = alpha[a];
        float4 o0, o1;
        o0.x = fmaf(aa, phit[0] - m0.x, m0.x);
        o0.y = fmaf(aa, phit[1] - m0.y, m0.y);
        o0.z = fmaf(aa, phit[2] - m0.z, m0.z);
        o0.w = fmaf(aa, phit[3] - m0.w, m0.w);
        o1.x = fmaf(aa, phit[4] - m1.x, m1.x);
        o1.y = fmaf(aa, phit[5] - m1.y, m1.y);
        o1.z = fmaf(aa, phit[6] - m1.z, m1.z);
        o1.w = fmaf(aa, phit[7] - m1.w, m1.w);
        float4* op = reinterpret_cast<float4*>(orow + a * 64);
        op[0] = o0;
        op[1] = o1;
    }
}

extern "C" void kernel_launch(void* const* d_in, const int* in_sizes, int n_in,
                              void* d_out, int out_size) {
    const float* x      = (const float*)d_in[0];
    const float* states = (const float*)d_in[1];
    const float* kr     = (const float*)d_in[2];
    const float* kt     = (const float*)d_in[3];
    const float* kphi   = (const float*)d_in[4];
    const float* ks     = (const float*)d_in[5];
    const float* br     = (const float*)d_in[6];
    const float* bt     = (const float*)d_in[7];
    const float* by     = (const float*)d_in[8];

    const int batch = in_sizes[0] / 64;

    float* out   = (float*)d_out;
    float* outst = out + (size_t)batch * 64;

    spdsru_prologue<<<1, 32>>>(kr, kt, kphi, ks, br, bt, by);

    int blocks = batch / 16;
    spdsru_main<<<blocks, 128>>>(x, states, out, outst);
}

// round 7
// speedup vs baseline: 1.3147x; 1.3147x over previous
#include <cuda_runtime.h>

#define A_NUM 5
#define EPSV 1e-10f

// ---------------- parameter block: device-computed, constant-consumed ------
struct Params {
    float4 Q4[48];   // Qt rows (16 float4), G rows (16), Qy rows (16)
    float  wr[8];    // yt weights (padded)
    float  wz[8];    // ws[a]*(1-alpha[a]) (padded)
    float  c;        // sum ws[a]*alpha[a]
    float  t;        // gate
    float  pad[2];
};

__device__   Params g_params;
__constant__ Params c_params;

// 8x8 Cayley transform: Q = inv(I - Bm) @ (I + Bm), Bm = L - L^T,
// L[i+1][c] = b[i+c] for c in [0, i]  (reference's mapping).
__device__ void cayley8(const float* __restrict__ b, float* __restrict__ Q) {
    float Bm[8][8];
    for (int i = 0; i < 8; i++)
        for (int j = 0; j < 8; j++) Bm[i][j] = 0.0f;
    for (int i = 0; i < 7; i++)
        for (int c = 0; c <= i; c++) Bm[i + 1][c] = b[i + c];

    float A[8][16];
    for (int i = 0; i < 8; i++) {
        for (int j = 0; j < 8; j++) {
            float v = Bm[i][j] - Bm[j][i];
            float d = (i == j) ? 1.0f : 0.0f;
            A[i][j]     = d - v;   // I - Bm
            A[i][j + 8] = d + v;   // I + Bm
        }
    }
    for (int k = 0; k < 8; k++) {
        int p = k;
        float best = fabsf(A[k][k]);
        for (int r = k + 1; r < 8; r++) {
            float v = fabsf(A[r][k]);
            if (v > best) { best = v; p = r; }
        }
        if (p != k) {
            for (int j = 0; j < 16; j++) {
                float tmp = A[k][j]; A[k][j] = A[p][j]; A[p][j] = tmp;
            }
        }
        float inv = 1.0f / A[k][k];
        for (int j = 0; j < 16; j++) A[k][j] *= inv;
        for (int r = 0; r < 8; r++) {
            if (r == k) continue;
            float f = A[r][k];
            for (int j = 0; j < 16; j++) A[r][j] -= f * A[k][j];
        }
    }
    for (int i = 0; i < 8; i++)
        for (int j = 0; j < 8; j++) Q[i * 8 + j] = A[i][j + 8];
}

__global__ void spdsru_prologue(const float* __restrict__ kr,
                                const float* __restrict__ kt,
                                const float* __restrict__ kphi,
                                const float* __restrict__ ks,
                                const float* __restrict__ br,
                                const float* __restrict__ bt,
                                const float* __restrict__ by) {
    __shared__ float sQr[64];
    __shared__ float sQt[64];
    int tid = threadIdx.x;
    float* Qflat = reinterpret_cast<float*>(g_params.Q4);
    if (tid < 3) {
        const float* bias = (tid == 0) ? br : ((tid == 1) ? bt : by);
        float Q[64];
        cayley8(bias, Q);
        if (tid == 0) {
            for (int i = 0; i < 64; i++) sQr[i] = Q[i];
        } else if (tid == 1) {
            for (int i = 0; i < 64; i++) { sQt[i] = Q[i]; Qflat[i] = Q[i]; }
        } else {
            for (int i = 0; i < 64; i++) Qflat[128 + i] = Q[i];
        }
    }
    __syncthreads();
    if (tid == 0) {
        // G = Qt @ Qr
        for (int i = 0; i < 8; i++) {
            for (int j = 0; j < 8; j++) {
                float s = 0.0f;
                for (int k = 0; k < 8; k++) s += sQt[i * 8 + k] * sQr[k * 8 + j];
                Qflat[64 + i * 8 + j] = s;
            }
        }
        const float alpha[A_NUM] = {0.01f, 0.25f, 0.5f, 0.9f, 0.99f};
        float r2[A_NUM], s2[A_NUM], sr = 0.0f, ss = 0.0f;
        for (int a = 0; a < A_NUM; a++) {
            r2[a] = kr[a] * kr[a]; sr += r2[a];
            s2[a] = ks[a] * ks[a]; ss += s2[a];
        }
        float ir = 1.0f / (sr + EPSV);
        float is = 1.0f / (ss + EPSV);
        float c = 0.0f;
        for (int a = 0; a < 8; a++) { g_params.wr[a] = 0.0f; g_params.wz[a] = 0.0f; }
        for (int a = 0; a < A_NUM; a++) {
            g_params.wr[a] = r2[a] * ir;
            float ws = s2[a] * is;
            g_params.wz[a] = ws * (1.0f - alpha[a]);
            c += ws * alpha[a];
        }
        g_params.c = c;
        float t2 = kt[0] * kt[0];
        g_params.t = t2 / (t2 + kphi[0] * kphi[0] + EPSV);
    }
}

// ---------------- main streaming kernel ----------------
// 128 threads/block = 16 batch elements; thread j of each 8-thread group owns
// row j of every 8x8 matrix. States stream through two linear reductions
// (yt, zt) in pass 1; pass 2 re-reads them (L1/L2 hits) for the Mt outputs.
// St = zt + c*Phit by linearity.
//
// Congruence C = Q*A*Q^T:
//   stage 1: B_row_j = A_row_j * Q^T   (Q rows from CONSTANT memory -> LDC,
//                                       off the L1tex pipe entirely)
//   stage 2: row j -> sB (STS.128), syncwarp,
//            C_row_j = sum_i Q[j][i]*B_row_i  (padded Q from smem, scalar).

template <int QB>   // base index into c_params.Q4 (float4 units)
__device__ __forceinline__ void congruence8(const float* a,
                                            const float* pQ,     // smem padded Q (stride 9)
                                            int j,
                                            float* bufbase,      // smem group tile (72 floats)
                                            float* c) {
    float bb[8];
#pragma unroll
    for (int k = 0; k < 8; k++) {
        float4 q0 = c_params.Q4[QB + 2 * k];
        float4 q1 = c_params.Q4[QB + 2 * k + 1];
        float s = a[0] * q0.x;
        s = fmaf(a[1], q0.y, s);
        s = fmaf(a[2], q0.z, s);
        s = fmaf(a[3], q0.w, s);
        s = fmaf(a[4], q1.x, s);
        s = fmaf(a[5], q1.y, s);
        s = fmaf(a[6], q1.z, s);
        s = fmaf(a[7], q1.w, s);
        bb[k] = s;
    }
    __syncwarp();   // previous congruence's reads of this buffer are done
    float4* bw = reinterpret_cast<float4*>(bufbase + j * 8);
    bw[0] = make_float4(bb[0], bb[1], bb[2], bb[3]);
    bw[1] = make_float4(bb[4], bb[5], bb[6], bb[7]);
    __syncwarp();   // all 8 rows visible before gathering
#pragma unroll
    for (int k = 0; k < 8; k++) c[k] = 0.0f;
#pragma unroll
    for (int i = 0; i < 8; i++) {
        float qji = pQ[j * 9 + i];
        const float4* br = reinterpret_cast<const float4*>(bufbase + i * 8);
        float4 b0 = br[0];
        float4 b1 = br[1];
        c[0] = fmaf(qji, b0.x, c[0]);
        c[1] = fmaf(qji, b0.y, c[1]);
        c[2] = fmaf(qji, b0.z, c[2]);
        c[3] = fmaf(qji, b0.w, c[3]);
        c[4] = fmaf(qji, b1.x, c[4]);
        c[5] = fmaf(qji, b1.y, c[5]);
        c[6] = fmaf(qji, b1.z, c[6]);
        c[7] = fmaf(qji, b1.w, c[7]);
    }
}

__global__ void __launch_bounds__(128, 8)
spdsru_main(const float* __restrict__ x,
            const float* __restrict__ states,
            float* __restrict__ out,
            float* __restrict__ outst) {
    __shared__ float sP[3 * 72];    // padded Qt | G | Qy (stride 9)
    __shared__ float sB[16 * 72];   // congruence scratch (4 warps * 4 groups)

    const int tid = threadIdx.x;
    if (tid < 64) {
        int r = tid >> 3, cc = tid & 7;
        const float* cf = reinterpret_cast<const float*>(c_params.Q4);
        sP[r * 9 + cc]       = cf[tid];         // Qt
        sP[72 + r * 9 + cc]  = cf[64 + tid];    // G
        sP[144 + r * 9 + cc] = cf[128 + tid];   // Qy
    }
    __syncthreads();

    const int grp = tid >> 3;            // 0..15
    const int j = tid & 7;
    const size_t b = (size_t)blockIdx.x * 16 + grp;
    float* bufbase = sB + grp * 72;

    // ---- load x row ----
    const float4* xp = reinterpret_cast<const float4*>(x + b * 64 + j * 8);
    float4 xa = xp[0], xb = xp[1];
    float xr[8] = {xa.x, xa.y, xa.z, xa.w, xb.x, xb.y, xb.z, xb.w};

    // ---- pass 1 over states: accumulate Yt and Zt, nothing stays live ----
    const float* mrow = states + b * 320 + j * 8;
    float yt[8], zt[8];
#pragma unroll
    for (int k = 0; k < 8; k++) { yt[k] = 0.0f; zt[k] = 0.0f; }
#pragma unroll
    for (int a = 0; a < A_NUM; a++) {
        const float4* mp = reinterpret_cast<const float4*>(mrow + a * 64);
        float4 m0 = mp[0], m1 = mp[1];
        float wa = c_params.wr[a], za = c_params.wz[a];
        yt[0] = fmaf(wa, m0.x, yt[0]);  zt[0] = fmaf(za, m0.x, zt[0]);
        yt[1] = fmaf(wa, m0.y, yt[1]);  zt[1] = fmaf(za, m0.y, zt[1]);
        yt[2] = fmaf(wa, m0.z, yt[2]);  zt[2] = fmaf(za, m0.z, zt[2]);
        yt[3] = fmaf(wa, m0.w, yt[3]);  zt[3] = fmaf(za, m0.w, zt[3]);
        yt[4] = fmaf(wa, m1.x, yt[4]);  zt[4] = fmaf(za, m1.x, zt[4]);
        yt[5] = fmaf(wa, m1.y, yt[5]);  zt[5] = fmaf(za, m1.y, zt[5]);
        yt[6] = fmaf(wa, m1.z, yt[6]);  zt[6] = fmaf(za, m1.z, zt[6]);
        yt[7] = fmaf(wa, m1.w, yt[7]);  zt[7] = fmaf(za, m1.w, zt[7]);
    }

    // ---- U = Qt*Xt*Qt^T ;  V = G*Yt*G^T  (G = Qt*Qr) ----
    float u[8], v[8];
    congruence8<0>(xr, sP, j, bufbase, u);
    congruence8<16>(yt, sP + 72, j, bufbase, v);

    // ---- Phit = (1-t)*U + t*V ----
    const float t = c_params.t;
    float phit[8];
#pragma unroll
    for (int k = 0; k < 8; k++) phit[k] = fmaf(t, v[k] - u[k], u[k]);

    // ---- St = Zt + c*Phit ;  Ot = Qy*St*Qy^T ; write output ----
    const float c = c_params.c;
    float st[8];
#pragma unroll
    for (int k = 0; k < 8; k++) st[k] = fmaf(c, phit[k], zt[k]);

    float ot[8];
    congruence8<32>(st, sP + 144, j, bufbase, ot);
    float4* oo = reinterpret_cast<float4*>(out + b * 64 + j * 8);
    oo[0] = make_float4(ot[0], ot[1], ot[2], ot[3]);
    oo[1] = make_float4(ot[4], ot[5], ot[6], ot[7]);

    // ---- pass 2 over states (cache hits): Mt[a] = m + alpha*(Phit - m) ----
    const float alpha[A_NUM] = {0.01f, 0.25f, 0.5f, 0.9f, 0.99f};
    float* orow = outst + b * 320 + j * 8;
#pragma unroll
    for (int a = 0; a < A_NUM; a++) {
        const float4* mp = reinterpret_cast<const float4*>(mrow + a * 64);
        float4 m0 = mp[0], m1 = mp[1];
        float aa = alpha[a];
        float4 o0, o1;
        o0.x = fmaf(aa, phit[0] - m0.x, m0.x);
        o0.y = fmaf(aa, phit[1] - m0.y, m0.y);
        o0.z = fmaf(aa, phit[2] - m0.z, m0.z);
        o0.w = fmaf(aa, phit[3] - m0.w, m0.w);
        o1.x = fmaf(aa, phit[4] - m1.x, m1.x);
        o1.y = fmaf(aa, phit[5] - m1.y, m1.y);
        o1.z = fmaf(aa, phit[6] - m1.z, m1.z);
        o1.w = fmaf(aa, phit[7] - m1.w, m1.w);
        float4* op = reinterpret_cast<float4*>(orow + a * 64);
        op[0] = o0;
        op[1] = o1;
    }
}

extern "C" void kernel_launch(void* const* d_in, const int* in_sizes, int n_in,
                              void* d_out, int out_size) {
    const float* x      = (const float*)d_in[0];
    const float* states = (const float*)d_in[1];
    const float* kr     = (const float*)d_in[2];
    const float* kt     = (const float*)d_in[3];
    const float* kphi   = (const float*)d_in[4];
    const float* ks     = (const float*)d_in[5];
    const float* br     = (const float*)d_in[6];
    const float* bt     = (const float*)d_in[7];
    const float* by     = (const float*)d_in[8];

    const int batch = in_sizes[0] / 64;

    float* out   = (float*)d_out;
    float* outst = out + (size_t)batch * 64;

    spdsru_prologue<<<1, 32>>>(kr, kt, kphi, ks, br, bt, by);

    // Copy the device-computed parameter block into __constant__ memory
    // (D2D async memcpy: graph-capturable, no allocation).
    void* csym = nullptr;
    void* dsym = nullptr;
    cudaGetSymbolAddress(&csym, c_params);
    cudaGetSymbolAddress(&dsym, g_params);
    cudaMemcpyAsync(csym, dsym, sizeof(Params), cudaMemcpyDeviceToDevice);

    int blocks = batch / 16;
    spdsru_main<<<blocks, 128>>>(x, states, out, outst);
}

// round 8
// speedup vs baseline: 1.5028x; 1.1431x over previous
#include <cuda_runtime.h>

#define A_NUM 5
#define EPSV 1e-10f

// ---------------- parameter block: device-computed, constant-consumed ------
struct Params {
    float4 Q4[48];   // Qt rows (16 float4), G rows (16), Qy rows (16)
    float  wr[8];    // yt weights (padded)
    float  ws[8];    // st weights (padded)
    float  t;        // gate
    float  pad[3];
};

__device__   Params g_params;
__constant__ Params c_params;

// 8x8 Cayley transform: Q = inv(I - Bm) @ (I + Bm), Bm = L - L^T,
// L[i+1][c] = b[i+c] for c in [0, i]  (reference's mapping).
__device__ void cayley8(const float* __restrict__ b, float* __restrict__ Q) {
    float Bm[8][8];
    for (int i = 0; i < 8; i++)
        for (int j = 0; j < 8; j++) Bm[i][j] = 0.0f;
    for (int i = 0; i < 7; i++)
        for (int c = 0; c <= i; c++) Bm[i + 1][c] = b[i + c];

    float A[8][16];
    for (int i = 0; i < 8; i++) {
        for (int j = 0; j < 8; j++) {
            float v = Bm[i][j] - Bm[j][i];
            float d = (i == j) ? 1.0f : 0.0f;
            A[i][j]     = d - v;   // I - Bm
            A[i][j + 8] = d + v;   // I + Bm
        }
    }
    for (int k = 0; k < 8; k++) {
        int p = k;
        float best = fabsf(A[k][k]);
        for (int r = k + 1; r < 8; r++) {
            float v = fabsf(A[r][k]);
            if (v > best) { best = v; p = r; }
        }
        if (p != k) {
            for (int j = 0; j < 16; j++) {
                float tmp = A[k][j]; A[k][j] = A[p][j]; A[p][j] = tmp;
            }
        }
        float inv = 1.0f / A[k][k];
        for (int j = 0; j < 16; j++) A[k][j] *= inv;
        for (int r = 0; r < 8; r++) {
            if (r == k) continue;
            float f = A[r][k];
            for (int j = 0; j < 16; j++) A[r][j] -= f * A[k][j];
        }
    }
    for (int i = 0; i < 8; i++)
        for (int j = 0; j < 8; j++) Q[i * 8 + j] = A[i][j + 8];
}

__global__ void spdsru_prologue(const float* __restrict__ kr,
                                const float* __restrict__ kt,
                                const float* __restrict__ kphi,
                                const float* __restrict__ ks,
                                const float* __restrict__ br,
                                const float* __restrict__ bt,
                                const float* __restrict__ by) {
    __shared__ float sQr[64];
    __shared__ float sQt[64];
    int tid = threadIdx.x;
    float* Qflat = reinterpret_cast<float*>(g_params.Q4);
    if (tid < 3) {
        const float* bias = (tid == 0) ? br : ((tid == 1) ? bt : by);
        float Q[64];
        cayley8(bias, Q);
        if (tid == 0) {
            for (int i = 0; i < 64; i++) sQr[i] = Q[i];
        } else if (tid == 1) {
            for (int i = 0; i < 64; i++) { sQt[i] = Q[i]; Qflat[i] = Q[i]; }
        } else {
            for (int i = 0; i < 64; i++) Qflat[128 + i] = Q[i];
        }
    }
    __syncthreads();
    if (tid == 0) {
        // G = Qt @ Qr
        for (int i = 0; i < 8; i++) {
            for (int j = 0; j < 8; j++) {
                float s = 0.0f;
                for (int k = 0; k < 8; k++) s += sQt[i * 8 + k] * sQr[k * 8 + j];
                Qflat[64 + i * 8 + j] = s;
            }
        }
        float r2[A_NUM], s2[A_NUM], sr = 0.0f, ss = 0.0f;
        for (int a = 0; a < A_NUM; a++) {
            r2[a] = kr[a] * kr[a]; sr += r2[a];
            s2[a] = ks[a] * ks[a]; ss += s2[a];
        }
        float ir = 1.0f / (sr + EPSV);
        float is = 1.0f / (ss + EPSV);
        for (int a = 0; a < 8; a++) { g_params.wr[a] = 0.0f; g_params.ws[a] = 0.0f; }
        for (int a = 0; a < A_NUM; a++) {
            g_params.wr[a] = r2[a] * ir;
            g_params.ws[a] = s2[a] * is;
        }
        float t2 = kt[0] * kt[0];
        g_params.t = t2 / (t2 + kphi[0] * kphi[0] + EPSV);
    }
}

// ---------------- main streaming kernel ----------------
// 128 threads/block = 16 batch elements; thread j of each 8-thread group owns
// row j of every 8x8 matrix. States stay REGISTER-RESIDENT (one global read,
// one global write — no re-read pass).
//
// Congruence C = Q*A*Q^T:
//   stage 1: B_row_j = A_row_j * Q^T   (Q rows from CONSTANT memory -> LDC,
//                                       off the L1tex pipe entirely)
//   stage 2: row j -> sB (STS.128), syncwarp,
//            C_row_j = sum_i Q[j][i]*B_row_i  (padded Q from smem, scalar;
//                                              B rows via broadcast LDS.128).

template <int QB>   // base index into c_params.Q4 (float4 units)
__device__ __forceinline__ void congruence8(const float* a,
                                            const float* pQ,     // smem padded Q (stride 9)
                                            int j,
                                            float* bufbase,      // smem group tile (72 floats)
                                            float* c) {
    float bb[8];
#pragma unroll
    for (int k = 0; k < 8; k++) {
        float4 q0 = c_params.Q4[QB + 2 * k];
        float4 q1 = c_params.Q4[QB + 2 * k + 1];
        float s = a[0] * q0.x;
        s = fmaf(a[1], q0.y, s);
        s = fmaf(a[2], q0.z, s);
        s = fmaf(a[3], q0.w, s);
        s = fmaf(a[4], q1.x, s);
        s = fmaf(a[5], q1.y, s);
        s = fmaf(a[6], q1.z, s);
        s = fmaf(a[7], q1.w, s);
        bb[k] = s;
    }
    __syncwarp();   // previous congruence's reads of this buffer are done
    float4* bw = reinterpret_cast<float4*>(bufbase + j * 8);
    bw[0] = make_float4(bb[0], bb[1], bb[2], bb[3]);
    bw[1] = make_float4(bb[4], bb[5], bb[6], bb[7]);
    __syncwarp();   // all 8 rows visible before gathering
#pragma unroll
    for (int k = 0; k < 8; k++) c[k] = 0.0f;
#pragma unroll
    for (int i = 0; i < 8; i++) {
        float qji = pQ[j * 9 + i];
        const float4* br = reinterpret_cast<const float4*>(bufbase + i * 8);
        float4 b0 = br[0];
        float4 b1 = br[1];
        c[0] = fmaf(qji, b0.x, c[0]);
        c[1] = fmaf(qji, b0.y, c[1]);
        c[2] = fmaf(qji, b0.z, c[2]);
        c[3] = fmaf(qji, b0.w, c[3]);
        c[4] = fmaf(qji, b1.x, c[4]);
        c[5] = fmaf(qji, b1.y, c[5]);
        c[6] = fmaf(qji, b1.z, c[6]);
        c[7] = fmaf(qji, b1.w, c[7]);
    }
}

__global__ void __launch_bounds__(128)
spdsru_main(const float* __restrict__ x,
            const float* __restrict__ states,
            float* __restrict__ out,
            float* __restrict__ outst) {
    __shared__ float sP[3 * 72];    // padded Qt | G | Qy (stride 9)
    __shared__ float sB[16 * 72];   // congruence scratch (4 warps * 4 groups)

    const int tid = threadIdx.x;
    if (tid < 64) {
        int r = tid >> 3, cc = tid & 7;
        const float* cf = reinterpret_cast<const float*>(c_params.Q4);
        sP[r * 9 + cc]       = cf[tid];         // Qt
        sP[72 + r * 9 + cc]  = cf[64 + tid];    // G
        sP[144 + r * 9 + cc] = cf[128 + tid];   // Qy
    }
    __syncthreads();

    const int grp = tid >> 3;            // 0..15
    const int j = tid & 7;
    const size_t b = (size_t)blockIdx.x * 16 + grp;
    float* bufbase = sB + grp * 72;

    // ---- load x row ----
    const float4* xp = reinterpret_cast<const float4*>(x + b * 64 + j * 8);
    float4 xa = xp[0], xb = xp[1];
    float xr[8] = {xa.x, xa.y, xa.z, xa.w, xb.x, xb.y, xb.z, xb.w};

    // ---- load state rows (register-resident), accumulate Yt in-flight ----
    float m[A_NUM][8];
    float yt[8];
#pragma unroll
    for (int k = 0; k < 8; k++) yt[k] = 0.0f;
#pragma unroll
    for (int a = 0; a < A_NUM; a++) {
        const float4* mp = reinterpret_cast<const float4*>(states + b * 320 + a * 64 + j * 8);
        float4 m0 = mp[0], m1 = mp[1];
        m[a][0] = m0.x; m[a][1] = m0.y; m[a][2] = m0.z; m[a][3] = m0.w;
        m[a][4] = m1.x; m[a][5] = m1.y; m[a][6] = m1.z; m[a][7] = m1.w;
        float wa = c_params.wr[a];
#pragma unroll
        for (int k = 0; k < 8; k++) yt[k] = fmaf(wa, m[a][k], yt[k]);
    }

    // ---- U = Qt*Xt*Qt^T ;  V = G*Yt*G^T  (G = Qt*Qr) ----
    float u[8], v[8];
    congruence8<0>(xr, sP, j, bufbase, u);
    congruence8<16>(yt, sP + 72, j, bufbase, v);

    // ---- Phit = (1-t)*U + t*V ----
    const float t = c_params.t;
    float phit[8];
#pragma unroll
    for (int k = 0; k < 8; k++) phit[k] = fmaf(t, v[k] - u[k], u[k]);

    // ---- Mt[a] = m + alpha*(Phit - m) ; St = sum ws[a]*Mt[a] ; write Mt ----
    const float alpha[A_NUM] = {0.01f, 0.25f, 0.5f, 0.9f, 0.99f};
    float st[8];
#pragma unroll
    for (int k = 0; k < 8; k++) st[k] = 0.0f;
#pragma unroll
    for (int a = 0; a < A_NUM; a++) {
        float mt[8];
        float wsa = c_params.ws[a];
#pragma unroll
        for (int k = 0; k < 8; k++) {
            mt[k] = fmaf(alpha[a], phit[k] - m[a][k], m[a][k]);
            st[k] = fmaf(wsa, mt[k], st[k]);
        }
        float4* op = reinterpret_cast<float4*>(outst + b * 320 + a * 64 + j * 8);
        op[0] = make_float4(mt[0], mt[1], mt[2], mt[3]);
        op[1] = make_float4(mt[4], mt[5], mt[6], mt[7]);
    }

    // ---- Ot = Qy * St * Qy^T ----
    float ot[8];
    congruence8<32>(st, sP + 144, j, bufbase, ot);
    float4* oo = reinterpret_cast<float4*>(out + b * 64 + j * 8);
    oo[0] = make_float4(ot[0], ot[1], ot[2], ot[3]);
    oo[1] = make_float4(ot[4], ot[5], ot[6], ot[7]);
}

extern "C" void kernel_launch(void* const* d_in, const int* in_sizes, int n_in,
                              void* d_out, int out_size) {
    const float* x      = (const float*)d_in[0];
    const float* states = (const float*)d_in[1];
    const float* kr     = (const float*)d_in[2];
    const float* kt     = (const float*)d_in[3];
    const float* kphi   = (const float*)d_in[4];
    const float* ks     = (const float*)d_in[5];
    const float* br     = (const float*)d_in[6];
    const float* bt     = (const float*)d_in[7];
    const float* by     = (const float*)d_in[8];

    const int batch = in_sizes[0] / 64;

    float* out   = (float*)d_out;
    float* outst = out + (size_t)batch * 64;

    spdsru_prologue<<<1, 32>>>(kr, kt, kphi, ks, br, bt, by);

    // Copy the device-computed parameter block into __constant__ memory
    // (D2D async memcpy: graph-capturable, no allocation).
    void* csym = nullptr;
    void* dsym = nullptr;
    cudaGetSymbolAddress(&csym, c_params);
    cudaGetSymbolAddress(&dsym, g_params);
    cudaMemcpyAsync(csym, dsym, sizeof(Params), cudaMemcpyDeviceToDevice);

    int blocks = batch / 16;
    spdsru_main<<<blocks, 128>>>(x, states, out, outst);
}

// round 9
// speedup vs baseline: 1.5919x; 1.0592x over previous
#include <cuda_runtime.h>

#define A_NUM 5
#define EPSV 1e-10f

// ---------------- parameter block: device-computed, constant-consumed ------
struct Params {
    float4 Q4[48];   // Qt rows (16 float4), G rows (16), Qy rows (16)
    float  wr[8];    // yt weights (padded)
    float  ws[8];    // st weights (padded)
    float  t;        // gate
    float  pad[3];
};

__device__   Params g_params;
__constant__ Params c_params;

// ---------------- warp-parallel prologue ----------------
// Lanes 0-7: Qr, lanes 8-15: Qt, lanes 16-23: Qy. Each lane owns one row of
// the augmented system [I-Bm | I+Bm]; Gauss-Jordan with partial pivoting via
// width-8 shuffles (no row swaps; pivot permutation tracked per-lane).
__global__ void spdsru_prologue(const float* __restrict__ kr,
                                const float* __restrict__ kt,
                                const float* __restrict__ kphi,
                                const float* __restrict__ ks,
                                const float* __restrict__ br,
                                const float* __restrict__ bt,
                                const float* __restrict__ by) {
    __shared__ float sQ[3][64];   // Qr, Qt, Qy row-major

    const int tid = threadIdx.x;
    float* Qflat = reinterpret_cast<float*>(g_params.Q4);

    if (tid < 24) {
        const int g = tid >> 3;        // matrix group 0..2
        const int r = tid & 7;         // my row
        const unsigned mask = 0xFFu << (g * 8);
        const float* bias = (g == 0) ? br : ((g == 1) ? bt : by);

        // Build row r of Bm = L - L^T with L[i+1][c] = b[i+c], c in [0, i].
        // L[r][j] = b[r-1+j] for j < r (when r >= 1); L^T[r][j] = L[j][r] =
        // b[j-1+r] for j > r.
        float a[16];
#pragma unroll
        for (int j = 0; j < 16; j++) a[j] = 0.0f;
        for (int j = 0; j < 8; j++) {
            float bm = 0.0f;
            if (j < r)      bm = bias[r - 1 + j];        // L
            else if (j > r) bm = -bias[j - 1 + r];       // -L^T
            float d = (j == r) ? 1.0f : 0.0f;
            a[j]     = d - bm;   // I - Bm
            a[j + 8] = d + bm;   // I + Bm
        }

        // Gauss-Jordan, partial pivoting, no swaps.
        bool used = false;
        int myk = -1;
        for (int k = 0; k < 8; k++) {
            // pivot = argmax |a[k]| over unused rows
            float v = used ? -1.0f : fabsf(a[k]);
            int idx = r;
#pragma unroll
            for (int off = 4; off > 0; off >>= 1) {
                float ov = __shfl_xor_sync(mask, v, off, 8);
                int   oi = __shfl_xor_sync(mask, idx, off, 8);
                if (ov > v || (ov == v && oi < idx)) { v = ov; idx = oi; }
            }
            const int p = idx;
            const float piv = __shfl_sync(mask, a[k], p, 8);
            const float invpiv = 1.0f / piv;
            const bool ispiv = (r == p);
            const float f = a[k];
#pragma unroll
            for (int j = 0; j < 16; j++) {
                float pj = __shfl_sync(mask, a[j], p, 8) * invpiv;
                a[j] = ispiv ? pj : fmaf(-f, pj, a[j]);
            }
            if (ispiv) { used = true; myk = k; }
        }

        // This lane holds solution row myk in a[8..15].
        for (int j = 0; j < 8; j++) sQ[g][myk * 8 + j] = a[8 + j];
    }
    __syncthreads();

    if (tid < 64) {
        // copy Qt, Qy; compute G = Qt @ Qr (one element per thread)
        Qflat[tid]       = sQ[1][tid];   // Qt
        Qflat[128 + tid] = sQ[2][tid];   // Qy
        const int i = tid >> 3, j = tid & 7;
        float s = 0.0f;
#pragma unroll
        for (int k = 0; k < 8; k++) s += sQ[1][i * 8 + k] * sQ[0][k * 8 + j];
        Qflat[64 + tid] = s;             // G
    } else if (tid == 64) {
        float r2[A_NUM], s2[A_NUM], sr = 0.0f, ss = 0.0f;
        for (int a = 0; a < A_NUM; a++) {
            r2[a] = kr[a] * kr[a]; sr += r2[a];
            s2[a] = ks[a] * ks[a]; ss += s2[a];
        }
        float ir = 1.0f / (sr + EPSV);
        float is = 1.0f / (ss + EPSV);
        for (int a = 0; a < 8; a++) { g_params.wr[a] = 0.0f; g_params.ws[a] = 0.0f; }
        for (int a = 0; a < A_NUM; a++) {
            g_params.wr[a] = r2[a] * ir;
            g_params.ws[a] = s2[a] * is;
        }
        float t2 = kt[0] * kt[0];
        g_params.t = t2 / (t2 + kphi[0] * kphi[0] + EPSV);
    }
}

// ---------------- main streaming kernel (UNCHANGED from R8) ----------------
// 128 threads/block = 16 batch elements; thread j of each 8-thread group owns
// row j of every 8x8 matrix. States stay REGISTER-RESIDENT.
// Congruence C = Q*A*Q^T:
//   stage 1: B_row_j = A_row_j * Q^T   (Q rows from CONSTANT memory -> LDC)
//   stage 2: row j -> sB (STS.128), syncwarp, gather via broadcast LDS.128.

template <int QB>   // base index into c_params.Q4 (float4 units)
__device__ __forceinline__ void congruence8(const float* a,
                                            const float* pQ,     // smem padded Q (stride 9)
                                            int j,
                                            float* bufbase,      // smem group tile (72 floats)
                                            float* c) {
    float bb[8];
#pragma unroll
    for (int k = 0; k < 8; k++) {
        float4 q0 = c_params.Q4[QB + 2 * k];
        float4 q1 = c_params.Q4[QB + 2 * k + 1];
        float s = a[0] * q0.x;
        s = fmaf(a[1], q0.y, s);
        s = fmaf(a[2], q0.z, s);
        s = fmaf(a[3], q0.w, s);
        s = fmaf(a[4], q1.x, s);
        s = fmaf(a[5], q1.y, s);
        s = fmaf(a[6], q1.z, s);
        s = fmaf(a[7], q1.w, s);
        bb[k] = s;
    }
    __syncwarp();
    float4* bw = reinterpret_cast<float4*>(bufbase + j * 8);
    bw[0] = make_float4(bb[0], bb[1], bb[2], bb[3]);
    bw[1] = make_float4(bb[4], bb[5], bb[6], bb[7]);
    __syncwarp();
#pragma unroll
    for (int k = 0; k < 8; k++) c[k] = 0.0f;
#pragma unroll
    for (int i = 0; i < 8; i++) {
        float qji = pQ[j * 9 + i];
        const float4* br = reinterpret_cast<const float4*>(bufbase + i * 8);
        float4 b0 = br[0];
        float4 b1 = br[1];
        c[0] = fmaf(qji, b0.x, c[0]);
        c[1] = fmaf(qji, b0.y, c[1]);
        c[2] = fmaf(qji, b0.z, c[2]);
        c[3] = fmaf(qji, b0.w, c[3]);
        c[4] = fmaf(qji, b1.x, c[4]);
        c[5] = fmaf(qji, b1.y, c[5]);
        c[6] = fmaf(qji, b1.z, c[6]);
        c[7] = fmaf(qji, b1.w, c[7]);
    }
}

__global__ void __launch_bounds__(128)
spdsru_main(const float* __restrict__ x,
            const float* __restrict__ states,
            float* __restrict__ out,
            float* __restrict__ outst) {
    __shared__ float sP[3 * 72];    // padded Qt | G | Qy (stride 9)
    __shared__ float sB[16 * 72];   // congruence scratch (4 warps * 4 groups)

    const int tid = threadIdx.x;
    if (tid < 64) {
        int r = tid >> 3, cc = tid & 7;
        const float* cf = reinterpret_cast<const float*>(c_params.Q4);
        sP[r * 9 + cc]       = cf[tid];         // Qt
        sP[72 + r * 9 + cc]  = cf[64 + tid];    // G
        sP[144 + r * 9 + cc] = cf[128 + tid];   // Qy
    }
    __syncthreads();

    const int grp = tid >> 3;            // 0..15
    const int j = tid & 7;
    const size_t b = (size_t)blockIdx.x * 16 + grp;
    float* bufbase = sB + grp * 72;

    // ---- load x row ----
    const float4* xp = reinterpret_cast<const float4*>(x + b * 64 + j * 8);
    float4 xa = xp[0], xb = xp[1];
    float xr[8] = {xa.x, xa.y, xa.z, xa.w, xb.x, xb.y, xb.z, xb.w};

    // ---- load state rows (register-resident), accumulate Yt in-flight ----
    float m[A_NUM][8];
    float yt[8];
#pragma unroll
    for (int k = 0; k < 8; k++) yt[k] = 0.0f;
#pragma unroll
    for (int a = 0; a < A_NUM; a++) {
        const float4* mp = reinterpret_cast<const float4*>(states + b * 320 + a * 64 + j * 8);
        float4 m0 = mp[0], m1 = mp[1];
        m[a][0] = m0.x; m[a][1] = m0.y; m[a][2] = m0.z; m[a][3] = m0.w;
        m[a][4] = m1.x; m[a][5] = m1.y; m[a][6] = m1.z; m[a][7] = m1.w;
        float wa = c_params.wr[a];
#pragma unroll
        for (int k = 0; k < 8; k++) yt[k] = fmaf(wa, m[a][k], yt[k]);
    }

    // ---- U = Qt*Xt*Qt^T ;  V = G*Yt*G^T  (G = Qt*Qr) ----
    float u[8], v[8];
    congruence8<0>(xr, sP, j, bufbase, u);
    congruence8<16>(yt, sP + 72, j, bufbase, v);

    // ---- Phit = (1-t)*U + t*V ----
    const float t = c_params.t;
    float phit[8];
#pragma unroll
    for (int k = 0; k < 8; k++) phit[k] = fmaf(t, v[k] - u[k], u[k]);

    // ---- Mt[a] = m + alpha*(Phit - m) ; St = sum ws[a]*Mt[a] ; write Mt ----
    const float alpha[A_NUM] = {0.01f, 0.25f, 0.5f, 0.9f, 0.99f};
    float st[8];
#pragma unroll
    for (int k = 0; k < 8; k++) st[k] = 0.0f;
#pragma unroll
    for (int a = 0; a < A_NUM; a++) {
        float mt[8];
        float wsa = c_params.ws[a];
#pragma unroll
        for (int k = 0; k < 8; k++) {
            mt[k] = fmaf(alpha[a], phit[k] - m[a][k], m[a][k]);
            st[k] = fmaf(wsa, mt[k], st[k]);
        }
        float4* op = reinterpret_cast<float4*>(outst + b * 320 + a * 64 + j * 8);
        op[0] = make_float4(mt[0], mt[1], mt[2], mt[3]);
        op[1] = make_float4(mt[4], mt[5], mt[6], mt[7]);
    }

    // ---- Ot = Qy * St * Qy^T ----
    float ot[8];
    congruence8<32>(st, sP + 144, j, bufbase, ot);
    float4* oo = reinterpret_cast<float4*>(out + b * 64 + j * 8);
    oo[0] = make_float4(ot[0], ot[1], ot[2], ot[3]);
    oo[1] = make_float4(ot[4], ot[5], ot[6], ot[7]);
}

extern "C" void kernel_launch(void* const* d_in, const int* in_sizes, int n_in,
                              void* d_out, int out_size) {
    const float* x      = (const float*)d_in[0];
    const float* states = (const float*)d_in[1];
    const float* kr     = (const float*)d_in[2];
    const float* kt     = (const float*)d_in[3];
    const float* kphi   = (const float*)d_in[4];
    const float* ks     = (const float*)d_in[5];
    const float* br     = (const float*)d_in[6];
    const float* bt     = (const float*)d_in[7];
    const float* by     = (const float*)d_in[8];

    const int batch = in_sizes[0] / 64;

    float* out   = (float*)d_out;
    float* outst = out + (size_t)batch * 64;

    spdsru_prologue<<<1, 128>>>(kr, kt, kphi, ks, br, bt, by);

    // Copy the device-computed parameter block into __constant__ memory
    // (D2D async memcpy: graph-capturable, no allocation).
    void* csym = nullptr;
    void* dsym = nullptr;
    cudaGetSymbolAddress(&csym, c_params);
    cudaGetSymbolAddress(&dsym, g_params);
    cudaMemcpyAsync(csym, dsym, sizeof(Params), cudaMemcpyDeviceToDevice);

    int blocks = batch / 16;
    spdsru_main<<<blocks, 128>>>(x, states, out, outst);
}